// round 4
// baseline (speedup 1.0000x reference)
#include <cuda_runtime.h>
#include <cstdint>
#include <math.h>

#define D        256
#define MC       1024
#define NTOK     65536
#define BM       128
#define BN       256
#define KC       32
#define LDP      36                      // padded row stride (floats)
#define A_BYTES  (BM * LDP * 4)          // 18432
#define B_BYTES  (BN * LDP * 4)          // 36864
#define STAGE_BYTES (A_BYTES + B_BYTES)  // 55296
#define OFF_SNE   0
#define OFF_RED   4096                   // best2 merge arrays: 4 * 2048 * 4B = 32KB
#define OFF_STAGE 36864
#define SMEM_TOTAL (OFF_STAGE + 2 * STAGE_BYTES)  // 147456
#define NCHUNKS  96                      // 4 nt * 3 pass * 8 kc

// ---- scratch (static, no allocations) ----
__device__ float g_xh[NTOK * D];
__device__ float g_xl[NTOK * D];
__device__ float g_eh[MC * D];
__device__ float g_el[MC * D];
__device__ float g_normX[NTOK];
__device__ float g_normE[MC];
__device__ int   g_c1[NTOK];
__device__ int   g_c2[NTOK];
__device__ int   g_indices[NTOK];
__device__ float g_counts[MC];
__device__ float g_sumsq;

static __device__ __forceinline__ uint32_t s2u(const void* p) {
    uint32_t a;
    asm("{ .reg .u64 t; cvta.to.shared.u64 t, %1; cvt.u32.u64 %0, t; }" : "=r"(a) : "l"(p));
    return a;
}
static __device__ __forceinline__ float tf32r(float a) {
    uint32_t r;
    asm("cvt.rna.tf32.f32 %0, %1;" : "=r"(r) : "f"(a));
    return __uint_as_float(r);
}
static __device__ __forceinline__ float fmarn(float a, float b, float c) {
    float d;
    asm("fma.rn.f32 %0, %1, %2, %3;" : "=f"(d) : "f"(a), "f"(b), "f"(c));
    return d;
}
#define CP_ASYNC16(dst, src) \
    asm volatile("cp.async.cg.shared.global [%0], [%1], 16;" :: "r"(dst), "l"(src))
#define CP_COMMIT()  asm volatile("cp.async.commit_group;" ::: "memory")
#define CP_WAIT(n)   asm volatile("cp.async.wait_group %0;" :: "n"(n) : "memory")

static __device__ __forceinline__ void mma_tf32(float& c0, float& c1, float& c2, float& c3,
                                                uint32_t a0, uint32_t a1, uint32_t a2, uint32_t a3,
                                                uint32_t b0, uint32_t b1) {
    asm volatile(
        "mma.sync.aligned.m16n8k8.row.col.f32.tf32.tf32.f32 "
        "{%0,%1,%2,%3}, {%4,%5,%6,%7}, {%8,%9}, {%0,%1,%2,%3};"
        : "+f"(c0), "+f"(c1), "+f"(c2), "+f"(c3)
        : "r"(a0), "r"(a1), "r"(a2), "r"(a3), "r"(b0), "r"(b1));
}

// ---------------- init ----------------
__global__ void init_kernel() {
    int t = threadIdx.x;
    if (t < MC) g_counts[t] = 0.0f;
    if (t == 0) g_sumsq = 0.0f;
}

// ---------------- tf32 split + row norms (norm arithmetic identical to R1) ----------------
__global__ void split_kernel(const float* __restrict__ src, int which) {
    int warp = threadIdx.x >> 5, lane = threadIdx.x & 31;
    int row = blockIdx.x * 8 + warp;
    float* hi = which ? g_eh : g_xh;
    float* lo = which ? g_el : g_xl;
    const float4* r4 = (const float4*)(src + ((size_t)row << 8));
    float4* h4 = (float4*)(hi + ((size_t)row << 8));
    float4* l4 = (float4*)(lo + ((size_t)row << 8));
    float s = 0.0f;
#pragma unroll
    for (int j = 0; j < 2; ++j) {
        float4 v = r4[lane + 32 * j];
        float4 h, l;
        h.x = tf32r(v.x); l.x = tf32r(v.x - h.x);
        h.y = tf32r(v.y); l.y = tf32r(v.y - h.y);
        h.z = tf32r(v.z); l.z = tf32r(v.z - h.z);
        h.w = tf32r(v.w); l.w = tf32r(v.w - h.w);
        h4[lane + 32 * j] = h; l4[lane + 32 * j] = l;
        s += v.x * v.x + v.y * v.y + v.z * v.z + v.w * v.w;
    }
#pragma unroll
    for (int o = 16; o > 0; o >>= 1) s += __shfl_xor_sync(0xffffffffu, s, o);
    if (lane == 0) {
        if (which) g_normE[row] = s; else g_normX[row] = s;
    }
}

// ---------------- mma.sync 3xTF32 distance GEMM + fused best-2 ----------------
__global__ __launch_bounds__(256, 1)
void mma_argmin_kernel() {
    extern __shared__ char smem[];
    uint32_t sb = s2u(smem);
    float* sne = (float*)(smem + OFF_SNE);
    float* sV1 = (float*)(smem + OFF_RED);          // [16][128]
    float* sV2 = sV1 + 2048;
    int*   sI1 = (int*)(sV2 + 2048);
    int*   sI2 = sI1 + 2048;

    int tid = threadIdx.x, wid = tid >> 5, lane = tid & 31;
    int warp_m = wid & 1, warp_n = wid >> 1;
    int lg = lane >> 2, lt = lane & 3;
    int row0 = blockIdx.x * BM;

    for (int i = tid; i < MC; i += 256) sne[i] = g_normE[i];

    float nx8[8];
#pragma unroll
    for (int mt = 0; mt < 4; ++mt)
#pragma unroll
        for (int i = 0; i < 2; ++i)
            nx8[mt * 2 + i] = g_normX[row0 + warp_m * 64 + mt * 16 + i * 8 + lg];

    float acc[4][8][4];
#pragma unroll
    for (int mt = 0; mt < 4; ++mt)
#pragma unroll
        for (int n8 = 0; n8 < 8; ++n8)
#pragma unroll
            for (int q = 0; q < 4; ++q) acc[mt][n8][q] = 0.0f;

    float bV1[8], bV2[8]; int bI1[8], bI2[8];
#pragma unroll
    for (int j = 0; j < 8; ++j) {
        bV1[j] = 3.4e38f; bI1[j] = 0x7fffffff;
        bV2[j] = 3.4e38f; bI2[j] = 0x7fffffff;
    }

    int a_r = tid >> 1, a_h = tid & 1;
    auto load_chunk = [&](int c) {
        int nt = c / 24, pass = (c / 8) % 3, kc = c & 7;
        const float* As = (pass < 2) ? g_xh : g_xl;
        const float* Bs = (pass == 1) ? g_el : g_eh;
        int kbase = kc * KC;
        uint32_t stage = sb + OFF_STAGE + (c & 1) * STAGE_BYTES;
        const float* asrc = As + ((size_t)(row0 + a_r) << 8) + kbase + a_h * 16;
        uint32_t adst = stage + a_r * (LDP * 4) + a_h * 64;
#pragma unroll
        for (int j = 0; j < 4; ++j) CP_ASYNC16(adst + j * 16, asrc + j * 4);
        const float* bsrc = Bs + ((size_t)(nt * BN + tid) << 8) + kbase;
        uint32_t bdst = stage + A_BYTES + tid * (LDP * 4);
#pragma unroll
        for (int j = 0; j < 8; ++j) CP_ASYNC16(bdst + j * 16, bsrc + j * 4);
    };

    __syncthreads();
    load_chunk(0);
    CP_COMMIT();

    for (int c = 0; c < NCHUNKS; ++c) {
        if (c + 1 < NCHUNKS) { load_chunk(c + 1); CP_COMMIT(); CP_WAIT(1); }
        else CP_WAIT(0);
        __syncthreads();

        const float* As = (const float*)(smem + OFF_STAGE + (c & 1) * STAGE_BYTES);
        const float* Bs = As + BM * LDP;

#pragma unroll
        for (int ks = 0; ks < 4; ++ks) {
            int k0 = ks * 8;
            uint32_t a[4][4], b[8][2];
#pragma unroll
            for (int mt = 0; mt < 4; ++mt) {
                int r = warp_m * 64 + mt * 16 + lg;
                a[mt][0] = *(const uint32_t*)&As[r * LDP + k0 + lt];
                a[mt][1] = *(const uint32_t*)&As[(r + 8) * LDP + k0 + lt];
                a[mt][2] = *(const uint32_t*)&As[r * LDP + k0 + 4 + lt];
                a[mt][3] = *(const uint32_t*)&As[(r + 8) * LDP + k0 + 4 + lt];
            }
#pragma unroll
            for (int n8 = 0; n8 < 8; ++n8) {
                int cn = warp_n * 64 + n8 * 8 + lg;
                b[n8][0] = *(const uint32_t*)&Bs[cn * LDP + k0 + lt];
                b[n8][1] = *(const uint32_t*)&Bs[cn * LDP + k0 + 4 + lt];
            }
#pragma unroll
            for (int mt = 0; mt < 4; ++mt)
#pragma unroll
                for (int n8 = 0; n8 < 8; ++n8)
                    mma_tf32(acc[mt][n8][0], acc[mt][n8][1], acc[mt][n8][2], acc[mt][n8][3],
                             a[mt][0], a[mt][1], a[mt][2], a[mt][3], b[n8][0], b[n8][1]);
        }
        __syncthreads();

        if ((c % 24) == 23) {
            int nt = c / 24;
#pragma unroll
            for (int mt = 0; mt < 4; ++mt)
#pragma unroll
                for (int n8 = 0; n8 < 8; ++n8) {
                    int cbase = nt * BN + warp_n * 64 + n8 * 8 + 2 * lt;
                    float ne0 = sne[cbase], ne1 = sne[cbase + 1];
                    float nxa = nx8[mt * 2], nxb = nx8[mt * 2 + 1];
                    float dd[2][2];
                    dd[0][0] = (ne0 + nxa) - 2.0f * acc[mt][n8][0];
                    dd[0][1] = (ne1 + nxa) - 2.0f * acc[mt][n8][1];
                    dd[1][0] = (ne0 + nxb) - 2.0f * acc[mt][n8][2];
                    dd[1][1] = (ne1 + nxb) - 2.0f * acc[mt][n8][3];
#pragma unroll
                    for (int i = 0; i < 2; ++i) {
                        int j = mt * 2 + i;
#pragma unroll
                        for (int q = 0; q < 2; ++q) {
                            float d = dd[i][q]; int cc = cbase + q;
                            if (d < bV1[j]) {
                                bV2[j] = bV1[j]; bI2[j] = bI1[j];
                                bV1[j] = d; bI1[j] = cc;
                            } else if (d < bV2[j]) {
                                bV2[j] = d; bI2[j] = cc;
                            }
                        }
                    }
                    acc[mt][n8][0] = 0.0f; acc[mt][n8][1] = 0.0f;
                    acc[mt][n8][2] = 0.0f; acc[mt][n8][3] = 0.0f;
                }
        }
    }

    // write per-thread best2 to smem: slot = warp_n*4+lt, row-local = ...
    __syncthreads();
    int slot = warp_n * 4 + lt;
#pragma unroll
    for (int j = 0; j < 8; ++j) {
        int mt = j >> 1, i = j & 1;
        int rl = warp_m * 64 + mt * 16 + i * 8 + lg;
        sV1[slot * 128 + rl] = bV1[j]; sI1[slot * 128 + rl] = bI1[j];
        sV2[slot * 128 + rl] = bV2[j]; sI2[slot * 128 + rl] = bI2[j];
    }
    __syncthreads();

    if (tid < BM) {
        float v1 = 3.4e38f, v2 = 3.4e38f; int i1 = 0x7fffffff, i2 = 0x7fffffff;
#pragma unroll
        for (int s = 0; s < 16; ++s) {
            float a1 = sV1[s * 128 + tid], a2 = sV2[s * 128 + tid];
            int   b1 = sI1[s * 128 + tid], b2 = sI2[s * 128 + tid];
            if (a1 < v1 || (a1 == v1 && b1 < i1)) {
                // new best1 = (a1,b1); second = better of old best1 and slot's a2
                if (v1 < a2 || (v1 == a2 && i1 < b2)) { v2 = v1; i2 = i1; }
                else { v2 = a2; i2 = b2; }
                v1 = a1; i1 = b1;
            } else if (a1 < v2 || (a1 == v2 && b1 < i2)) {
                v2 = a1; i2 = b1;
            }
        }
        g_c1[row0 + tid] = i1;
        g_c2[row0 + tid] = i2;
    }
}

// ---------------- exact fp32 refinement (bitwise-R1 arithmetic) ----------------
__global__ void refine_kernel(const float* __restrict__ x, const float* __restrict__ emb,
                              float* __restrict__ d_out, long long idx_off, int write_idx) {
    int row = blockIdx.x * blockDim.x + threadIdx.x;
    if (row >= NTOK) return;
    int i1 = g_c1[row], i2 = g_c2[row];
    const float4* x4 = (const float4*)(x + ((size_t)row << 8));
    const float4* e14 = (const float4*)(emb + ((size_t)i1 << 8));
    const float4* e24 = (const float4*)(emb + ((size_t)i2 << 8));
    float dot1 = 0.0f, dot2 = 0.0f;
#pragma unroll 8
    for (int c = 0; c < 64; ++c) {
        float4 xv = __ldg(&x4[c]);
        float4 a = __ldg(&e14[c]);
        float4 b = __ldg(&e24[c]);
        dot1 = fmarn(xv.x, a.x, dot1); dot1 = fmarn(xv.y, a.y, dot1);
        dot1 = fmarn(xv.z, a.z, dot1); dot1 = fmarn(xv.w, a.w, dot1);
        dot2 = fmarn(xv.x, b.x, dot2); dot2 = fmarn(xv.y, b.y, dot2);
        dot2 = fmarn(xv.z, b.z, dot2); dot2 = fmarn(xv.w, b.w, dot2);
    }
    float nx = g_normX[row];
    float d1 = (nx + g_normE[i1]) - 2.0f * dot1;
    float d2 = (nx + g_normE[i2]) - 2.0f * dot2;
    int win = (d2 < d1 || (d2 == d1 && i2 < i1)) ? i2 : i1;
    g_indices[row] = win;
    if (write_idx) d_out[idx_off + row] = (float)win;
}

// ---------------- gather + straight-through + loss + histogram ----------------
__global__ void gather_kernel(const float* __restrict__ x, const float* __restrict__ emb,
                              float* __restrict__ qst_out) {
    int warp = threadIdx.x >> 5, lane = threadIdx.x & 31;
    int row = blockIdx.x * 8 + warp;
    int idx = g_indices[row];
    const float4* e4 = (const float4*)(emb + ((size_t)idx << 8));
    const float4* x4 = (const float4*)(x + ((size_t)row << 8));
    float4* o4 = (float4*)(qst_out + ((size_t)row << 8));
    float s = 0.0f;
#pragma unroll
    for (int j = 0; j < 2; ++j) {
        float4 q = e4[lane + 32 * j];
        float4 xv = x4[lane + 32 * j];
        float4 o;
        o.x = xv.x + (q.x - xv.x);
        o.y = xv.y + (q.y - xv.y);
        o.z = xv.z + (q.z - xv.z);
        o.w = xv.w + (q.w - xv.w);
        o4[lane + 32 * j] = o;
        float dx = xv.x - q.x, dy = xv.y - q.y, dz = xv.z - q.z, dw = xv.w - q.w;
        s += dx * dx + dy * dy + dz * dz + dw * dw;
    }
#pragma unroll
    for (int o = 16; o > 0; o >>= 1) s += __shfl_xor_sync(0xffffffffu, s, o);
    if (lane == 0) {
        atomicAdd(&g_sumsq, s);
        atomicAdd(&g_counts[idx], 1.0f);
    }
}

// ---------------- loss + perplexity ----------------
__global__ void finalize_kernel(float* __restrict__ d_out, long long loss_off,
                                long long perp_off) {
    __shared__ float red[1024];
    int t = threadIdx.x;
    float p = g_counts[t] * (1.0f / (float)NTOK);
    red[t] = p * logf(p + 1e-10f);
    __syncthreads();
    for (int s = 512; s > 0; s >>= 1) {
        if (t < s) red[t] += red[t + s];
        __syncthreads();
    }
    if (t == 0) {
        d_out[loss_off] = 0.25f * g_sumsq / ((float)NTOK * (float)D);
        d_out[perp_off] = expf(-red[0]);
    }
}

// ---------------- launch ----------------
extern "C" void kernel_launch(void* const* d_in, const int* in_sizes, int n_in,
                              void* d_out, int out_size) {
    const float* x   = (const float*)d_in[0];
    const float* emb = (const float*)d_in[1];
    float* out = (float*)d_out;

    int NT = in_sizes[0] / D;
    long long qn = (long long)in_sizes[0];
    long long loss_off = qn;
    long long idx_off  = qn + 1;
    long long perp_off = qn + 1 + NT;
    int full = (out_size >= (int)(qn + NT + 2)) ? 1 : 0;

    cudaFuncSetAttribute(mma_argmin_kernel, cudaFuncAttributeMaxDynamicSharedMemorySize,
                         SMEM_TOTAL);

    init_kernel<<<1, 1024>>>();
    split_kernel<<<NT / 8, 256>>>(x, 0);
    split_kernel<<<MC / 8, 256>>>(emb, 1);
    mma_argmin_kernel<<<NT / BM, 256, SMEM_TOTAL>>>();
    refine_kernel<<<NT / 256, 256>>>(x, emb, out, idx_off, full);
    gather_kernel<<<NT / 8, 256>>>(x, emb, out);
    if (full) finalize_kernel<<<1, 1024>>>(out, loss_off, perp_off);
}

// round 6
// speedup vs baseline: 1.8464x; 1.8464x over previous
#include <cuda_runtime.h>
#include <cstdint>
#include <math.h>

#define D        256
#define MC       1024
#define NTOK     65536
#define BM       128
#define BN       256
#define KC       32
#define LDP      36                      // padded row stride (floats)
#define A_BYTES  (BM * LDP * 4)          // 18432
#define B_BYTES  (BN * LDP * 4)          // 36864
#define STAGE_BYTES (A_BYTES + B_BYTES)  // 55296
#define NSTAGE   3
#define OFF_SNE   0
#define OFF_STAGE 4096
#define SMEM_TOTAL (OFF_STAGE + NSTAGE * STAGE_BYTES)  // 169984
#define NCHUNKS  32                      // 4 nt * 8 kc (single pass)
#define NCAND    8

// ---- scratch (static, no allocations) ----
__device__ float g_xh[NTOK * D];         // tf32-rounded x
__device__ float g_eh[MC * D];           // tf32-rounded e
__device__ float g_normX[NTOK];
__device__ float g_normE[MC];
__device__ int   g_cand[NTOK * NCAND];
__device__ int   g_indices[NTOK];
__device__ float g_counts[MC];
__device__ float g_sumsq;

static __device__ __forceinline__ uint32_t s2u(const void* p) {
    uint32_t a;
    asm("{ .reg .u64 t; cvta.to.shared.u64 t, %1; cvt.u32.u64 %0, t; }" : "=r"(a) : "l"(p));
    return a;
}
static __device__ __forceinline__ float tf32r(float a) {
    uint32_t r;
    asm("cvt.rna.tf32.f32 %0, %1;" : "=r"(r) : "f"(a));
    return __uint_as_float(r);
}
static __device__ __forceinline__ float fmarn(float a, float b, float c) {
    float d;
    asm("fma.rn.f32 %0, %1, %2, %3;" : "=f"(d) : "f"(a), "f"(b), "f"(c));
    return d;
}
#define CP_ASYNC16(dst, src) \
    asm volatile("cp.async.cg.shared.global [%0], [%1], 16;" :: "r"(dst), "l"(src))
#define CP_COMMIT()  asm volatile("cp.async.commit_group;" ::: "memory")
#define CP_WAIT(n)   asm volatile("cp.async.wait_group %0;" :: "n"(n) : "memory")

static __device__ __forceinline__ void mma_tf32(float& c0, float& c1, float& c2, float& c3,
                                                uint32_t a0, uint32_t a1, uint32_t a2, uint32_t a3,
                                                uint32_t b0, uint32_t b1) {
    asm volatile(
        "mma.sync.aligned.m16n8k8.row.col.f32.tf32.tf32.f32 "
        "{%0,%1,%2,%3}, {%4,%5,%6,%7}, {%8,%9}, {%0,%1,%2,%3};"
        : "+f"(c0), "+f"(c1), "+f"(c2), "+f"(c3)
        : "r"(a0), "r"(a1), "r"(a2), "r"(a3), "r"(b0), "r"(b1));
}

// ---------------- init ----------------
__global__ void init_kernel() {
    int t = threadIdx.x;
    if (t < MC) g_counts[t] = 0.0f;
    if (t == 0) g_sumsq = 0.0f;
}

// ---------------- tf32 round + exact row norms ----------------
__global__ void split_kernel(const float* __restrict__ src, int which) {
    int warp = threadIdx.x >> 5, lane = threadIdx.x & 31;
    int row = blockIdx.x * 8 + warp;
    float* hi = which ? g_eh : g_xh;
    const float4* r4 = (const float4*)(src + ((size_t)row << 8));
    float4* h4 = (float4*)(hi + ((size_t)row << 8));
    float s = 0.0f;
#pragma unroll
    for (int j = 0; j < 2; ++j) {
        float4 v = r4[lane + 32 * j];
        float4 h;
        h.x = tf32r(v.x); h.y = tf32r(v.y); h.z = tf32r(v.z); h.w = tf32r(v.w);
        h4[lane + 32 * j] = h;
        s += v.x * v.x + v.y * v.y + v.z * v.z + v.w * v.w;
    }
#pragma unroll
    for (int o = 16; o > 0; o >>= 1) s += __shfl_xor_sync(0xffffffffu, s, o);
    if (lane == 0) {
        if (which) g_normE[row] = s; else g_normX[row] = s;
    }
}

// ---------------- single-pass TF32 distance GEMM + fused best-2 / row top-8 ----------------
__global__ __launch_bounds__(256, 1)
void mma_argmin_kernel() {
    extern __shared__ char smem[];
    uint32_t sb = s2u(smem);
    float* sne = (float*)(smem + OFF_SNE);
    // merge arrays alias stage memory (used only after mainloop)
    float* sV1 = (float*)(smem + OFF_STAGE);        // [16][128]
    float* sV2 = sV1 + 2048;
    int*   sI1 = (int*)(sV2 + 2048);
    int*   sI2 = sI1 + 2048;

    int tid = threadIdx.x, wid = tid >> 5, lane = tid & 31;
    int warp_m = wid & 1, warp_n = wid >> 1;
    int lg = lane >> 2, lt = lane & 3;
    int row0 = blockIdx.x * BM;

    for (int i = tid; i < MC; i += 256) sne[i] = g_normE[i];

    float nx8[8];
#pragma unroll
    for (int mt = 0; mt < 4; ++mt)
#pragma unroll
        for (int i = 0; i < 2; ++i)
            nx8[mt * 2 + i] = g_normX[row0 + warp_m * 64 + mt * 16 + i * 8 + lg];

    float acc[4][8][4];
#pragma unroll
    for (int mt = 0; mt < 4; ++mt)
#pragma unroll
        for (int n8 = 0; n8 < 8; ++n8)
#pragma unroll
            for (int q = 0; q < 4; ++q) acc[mt][n8][q] = 0.0f;

    float bV1[8], bV2[8]; int bI1[8], bI2[8];
#pragma unroll
    for (int j = 0; j < 8; ++j) {
        bV1[j] = 3.4e38f; bI1[j] = 0x7fffffff;
        bV2[j] = 3.4e38f; bI2[j] = 0x7fffffff;
    }

    int a_r = tid >> 1, a_h = tid & 1;
    auto load_chunk = [&](int c) {
        int nt = c >> 3, kc = c & 7;
        int kbase = kc * KC;
        uint32_t stage = sb + OFF_STAGE + (c % NSTAGE) * STAGE_BYTES;
        const float* asrc = g_xh + ((size_t)(row0 + a_r) << 8) + kbase + a_h * 16;
        uint32_t adst = stage + a_r * (LDP * 4) + a_h * 64;
#pragma unroll
        for (int j = 0; j < 4; ++j) CP_ASYNC16(adst + j * 16, asrc + j * 4);
        const float* bsrc = g_eh + ((size_t)(nt * BN + tid) << 8) + kbase;
        uint32_t bdst = stage + A_BYTES + tid * (LDP * 4);
#pragma unroll
        for (int j = 0; j < 8; ++j) CP_ASYNC16(bdst + j * 16, bsrc + j * 4);
    };

    load_chunk(0); CP_COMMIT();
    load_chunk(1); CP_COMMIT();

    for (int c = 0; c < NCHUNKS; ++c) {
        if (c + 2 < NCHUNKS) CP_WAIT(1); else CP_WAIT(0);
        __syncthreads();                         // chunk c visible; all readers past stage (c+2)%3
        if (c + 2 < NCHUNKS) { load_chunk(c + 2); CP_COMMIT(); }

        const float* As = (const float*)(smem + OFF_STAGE + (c % NSTAGE) * STAGE_BYTES);
        const float* Bs = As + BM * LDP;

#pragma unroll
        for (int ks = 0; ks < 4; ++ks) {
            int k0 = ks * 8;
            uint32_t a[4][4], b[8][2];
#pragma unroll
            for (int mt = 0; mt < 4; ++mt) {
                int r = warp_m * 64 + mt * 16 + lg;
                a[mt][0] = *(const uint32_t*)&As[r * LDP + k0 + lt];
                a[mt][1] = *(const uint32_t*)&As[(r + 8) * LDP + k0 + lt];
                a[mt][2] = *(const uint32_t*)&As[r * LDP + k0 + 4 + lt];
                a[mt][3] = *(const uint32_t*)&As[(r + 8) * LDP + k0 + 4 + lt];
            }
#pragma unroll
            for (int n8 = 0; n8 < 8; ++n8) {
                int cn = warp_n * 64 + n8 * 8 + lg;
                b[n8][0] = *(const uint32_t*)&Bs[cn * LDP + k0 + lt];
                b[n8][1] = *(const uint32_t*)&Bs[cn * LDP + k0 + 4 + lt];
            }
#pragma unroll
            for (int mt = 0; mt < 4; ++mt)
#pragma unroll
                for (int n8 = 0; n8 < 8; ++n8)
                    mma_tf32(acc[mt][n8][0], acc[mt][n8][1], acc[mt][n8][2], acc[mt][n8][3],
                             a[mt][0], a[mt][1], a[mt][2], a[mt][3], b[n8][0], b[n8][1]);
        }

        if ((c & 7) == 7) {
            int nt = c >> 3;
#pragma unroll
            for (int mt = 0; mt < 4; ++mt)
#pragma unroll
                for (int n8 = 0; n8 < 8; ++n8) {
                    int cbase = nt * BN + warp_n * 64 + n8 * 8 + 2 * lt;
                    float ne0 = sne[cbase], ne1 = sne[cbase + 1];
                    float nxa = nx8[mt * 2], nxb = nx8[mt * 2 + 1];
                    float dd[2][2];
                    dd[0][0] = (ne0 + nxa) - 2.0f * acc[mt][n8][0];
                    dd[0][1] = (ne1 + nxa) - 2.0f * acc[mt][n8][1];
                    dd[1][0] = (ne0 + nxb) - 2.0f * acc[mt][n8][2];
                    dd[1][1] = (ne1 + nxb) - 2.0f * acc[mt][n8][3];
#pragma unroll
                    for (int i = 0; i < 2; ++i) {
                        int j = mt * 2 + i;
#pragma unroll
                        for (int q = 0; q < 2; ++q) {
                            float d = dd[i][q]; int cc = cbase + q;
                            if (d < bV1[j]) {
                                bV2[j] = bV1[j]; bI2[j] = bI1[j];
                                bV1[j] = d; bI1[j] = cc;
                            } else if (d < bV2[j]) {
                                bV2[j] = d; bI2[j] = cc;
                            }
                        }
                    }
                    acc[mt][n8][0] = 0.0f; acc[mt][n8][1] = 0.0f;
                    acc[mt][n8][2] = 0.0f; acc[mt][n8][3] = 0.0f;
                }
        }
    }

    // per-thread best2 -> smem (alias stage region; all compute done)
    __syncthreads();
    int slot = warp_n * 4 + lt;
#pragma unroll
    for (int j = 0; j < 8; ++j) {
        int mt = j >> 1, i = j & 1;
        int rl = warp_m * 64 + mt * 16 + i * 8 + lg;
        sV1[slot * 128 + rl] = bV1[j]; sI1[slot * 128 + rl] = bI1[j];
        sV2[slot * 128 + rl] = bV2[j]; sI2[slot * 128 + rl] = bI2[j];
    }
    __syncthreads();

    // row-level top-8 of the 32 candidates (register-resident selection)
    if (tid < BM) {
        float v[32]; int ii[32];
#pragma unroll
        for (int s = 0; s < 16; ++s) {
            v[2 * s]     = sV1[s * 128 + tid]; ii[2 * s]     = sI1[s * 128 + tid];
            v[2 * s + 1] = sV2[s * 128 + tid]; ii[2 * s + 1] = sI2[s * 128 + tid];
        }
        unsigned used = 0;
#pragma unroll 1
        for (int sel = 0; sel < NCAND; ++sel) {
            float bv = 3.4e38f; int bi = 0x7fffffff; int bs = 0;
#pragma unroll
            for (int s = 0; s < 32; ++s) {
                bool ok = !((used >> s) & 1u);
                if (ok && (v[s] < bv || (v[s] == bv && ii[s] < bi))) {
                    bv = v[s]; bi = ii[s]; bs = s;
                }
            }
            used |= 1u << bs;
            g_cand[(size_t)(row0 + tid) * NCAND + sel] = bi;
        }
    }
}

// ---------------- exact fp32 refinement over 8 candidates (R1 arithmetic) ----------------
__global__ void refine_kernel(const float* __restrict__ x, const float* __restrict__ emb,
                              float* __restrict__ d_out, long long idx_off, int write_idx) {
    int row = blockIdx.x * blockDim.x + threadIdx.x;
    if (row >= NTOK) return;
    int ci[NCAND];
    const float4* c4[NCAND];
#pragma unroll
    for (int j = 0; j < NCAND; ++j) {
        ci[j] = g_cand[(size_t)row * NCAND + j];
        c4[j] = (const float4*)(emb + ((size_t)ci[j] << 8));
    }
    const float4* x4 = (const float4*)(x + ((size_t)row << 8));
    float acc[NCAND];
#pragma unroll
    for (int j = 0; j < NCAND; ++j) acc[j] = 0.0f;
#pragma unroll 4
    for (int k = 0; k < 64; ++k) {
        float4 xv = __ldg(&x4[k]);
#pragma unroll
        for (int j = 0; j < NCAND; ++j) {
            float4 e = __ldg(&c4[j][k]);
            acc[j] = fmarn(xv.x, e.x, acc[j]);
            acc[j] = fmarn(xv.y, e.y, acc[j]);
            acc[j] = fmarn(xv.z, e.z, acc[j]);
            acc[j] = fmarn(xv.w, e.w, acc[j]);
        }
    }
    float nx = g_normX[row];
    float bv = 3.4e38f; int bi = 0x7fffffff;
#pragma unroll
    for (int j = 0; j < NCAND; ++j) {
        float d = (nx + g_normE[ci[j]]) - 2.0f * acc[j];
        if (d < bv || (d == bv && ci[j] < bi)) { bv = d; bi = ci[j]; }
    }
    g_indices[row] = bi;
    if (write_idx) d_out[idx_off + row] = (float)bi;
}

// ---------------- gather + straight-through + loss + histogram ----------------
__global__ void gather_kernel(const float* __restrict__ x, const float* __restrict__ emb,
                              float* __restrict__ qst_out) {
    int warp = threadIdx.x >> 5, lane = threadIdx.x & 31;
    int row = blockIdx.x * 8 + warp;
    int idx = g_indices[row];
    const float4* e4 = (const float4*)(emb + ((size_t)idx << 8));
    const float4* x4 = (const float4*)(x + ((size_t)row << 8));
    float4* o4 = (float4*)(qst_out + ((size_t)row << 8));
    float s = 0.0f;
#pragma unroll
    for (int j = 0; j < 2; ++j) {
        float4 q = e4[lane + 32 * j];
        float4 xv = x4[lane + 32 * j];
        float4 o;
        o.x = xv.x + (q.x - xv.x);
        o.y = xv.y + (q.y - xv.y);
        o.z = xv.z + (q.z - xv.z);
        o.w = xv.w + (q.w - xv.w);
        o4[lane + 32 * j] = o;
        float dx = xv.x - q.x, dy = xv.y - q.y, dz = xv.z - q.z, dw = xv.w - q.w;
        s += dx * dx + dy * dy + dz * dz + dw * dw;
    }
#pragma unroll
    for (int o = 16; o > 0; o >>= 1) s += __shfl_xor_sync(0xffffffffu, s, o);
    if (lane == 0) {
        atomicAdd(&g_sumsq, s);
        atomicAdd(&g_counts[idx], 1.0f);
    }
}

// ---------------- loss + perplexity ----------------
__global__ void finalize_kernel(float* __restrict__ d_out, long long loss_off,
                                long long perp_off) {
    __shared__ float red[1024];
    int t = threadIdx.x;
    float p = g_counts[t] * (1.0f / (float)NTOK);
    red[t] = p * logf(p + 1e-10f);
    __syncthreads();
    for (int s = 512; s > 0; s >>= 1) {
        if (t < s) red[t] += red[t + s];
        __syncthreads();
    }
    if (t == 0) {
        d_out[loss_off] = 0.25f * g_sumsq / ((float)NTOK * (float)D);
        d_out[perp_off] = expf(-red[0]);
    }
}

// ---------------- launch ----------------
extern "C" void kernel_launch(void* const* d_in, const int* in_sizes, int n_in,
                              void* d_out, int out_size) {
    const float* x   = (const float*)d_in[0];
    const float* emb = (const float*)d_in[1];
    float* out = (float*)d_out;

    int NT = in_sizes[0] / D;
    long long qn = (long long)in_sizes[0];
    long long loss_off = qn;
    long long idx_off  = qn + 1;
    long long perp_off = qn + 1 + NT;
    int full = (out_size >= (int)(qn + NT + 2)) ? 1 : 0;

    cudaFuncSetAttribute(mma_argmin_kernel, cudaFuncAttributeMaxDynamicSharedMemorySize,
                         SMEM_TOTAL);

    init_kernel<<<1, 1024>>>();
    split_kernel<<<NT / 8, 256>>>(x, 0);
    split_kernel<<<MC / 8, 256>>>(emb, 1);
    mma_argmin_kernel<<<NT / BM, 256, SMEM_TOTAL>>>();
    refine_kernel<<<NT / 256, 256>>>(x, emb, out, idx_off, full);
    gather_kernel<<<NT / 8, 256>>>(x, emb, out);
    if (full) finalize_kernel<<<1, 1024>>>(out, loss_off, perp_off);
}

// round 9
// speedup vs baseline: 2.1723x; 1.1765x over previous
#include <cuda_runtime.h>
#include <cstdint>
#include <math.h>

#define D        256
#define MC       1024
#define NTOK     65536
#define BM       128
#define BN       256
#define KC       32
#define LDP      36                       // padded row stride (floats)
#define A_BYTES  (BM * LDP * 4)           // 18432
#define B_BYTES  (BN * LDP * 4)           // 36864
#define STAGE_BYTES (A_BYTES + B_BYTES)   // 55296
#define OFF_SNE   0
#define OFF_RED   4096                    // 4 arrays [32][128] = 64KB
#define OFF_STAGE 69632
#define SMEM_TOTAL (OFF_STAGE + 2 * STAGE_BYTES)   // 180224
#define NCHUNKS  32                       // 4 nt * 8 kc
#define NCAND    8
#define FINF     3.4e38f
#define IMAX     0x7fffffff
#define ELD      260                      // candidate-row smem stride (floats)

// ---- scratch (static, no allocations) ----
__device__ float g_xh[NTOK * D];          // tf32-rounded x
__device__ float g_eh[MC * D];            // tf32-rounded e
__device__ float g_normX[NTOK];
__device__ float g_normE[MC];
__device__ int   g_cand[NTOK * NCAND];
__device__ float g_counts[MC];
__device__ float g_sumsq;

static __device__ __forceinline__ uint32_t s2u(const void* p) {
    uint32_t a;
    asm("{ .reg .u64 t; cvta.to.shared.u64 t, %1; cvt.u32.u64 %0, t; }" : "=r"(a) : "l"(p));
    return a;
}
static __device__ __forceinline__ float tf32r(float a) {
    uint32_t r;
    asm("cvt.rna.tf32.f32 %0, %1;" : "=r"(r) : "f"(a));
    return __uint_as_float(r);
}
static __device__ __forceinline__ float fmarn(float a, float b, float c) {
    float d;
    asm("fma.rn.f32 %0, %1, %2, %3;" : "=f"(d) : "f"(a), "f"(b), "f"(c));
    return d;
}
#define CP_ASYNC16(dst, src) \
    asm volatile("cp.async.cg.shared.global [%0], [%1], 16;" :: "r"(dst), "l"(src))
#define CP_COMMIT()  asm volatile("cp.async.commit_group;" ::: "memory")
#define CP_WAIT(n)   asm volatile("cp.async.wait_group %0;" :: "n"(n) : "memory")

static __device__ __forceinline__ void mma_tf32(float& c0, float& c1, float& c2, float& c3,
                                                uint32_t a0, uint32_t a1, uint32_t a2, uint32_t a3,
                                                uint32_t b0, uint32_t b1) {
    asm volatile(
        "mma.sync.aligned.m16n8k8.row.col.f32.tf32.tf32.f32 "
        "{%0,%1,%2,%3}, {%4,%5,%6,%7}, {%8,%9}, {%0,%1,%2,%3};"
        : "+f"(c0), "+f"(c1), "+f"(c2), "+f"(c3)
        : "r"(a0), "r"(a1), "r"(a2), "r"(a3), "r"(b0), "r"(b1));
}

// ---------------- init ----------------
__global__ void init_kernel() {
    int t = threadIdx.x;
    if (t < MC) g_counts[t] = 0.0f;
    if (t == 0) g_sumsq = 0.0f;
}

// ---------------- tf32 round + exact row norms (bitwise-R1 norm arithmetic) ----------------
__global__ void split_kernel(const float* __restrict__ src, int which) {
    int warp = threadIdx.x >> 5, lane = threadIdx.x & 31;
    int row = blockIdx.x * 8 + warp;
    float* hi = which ? g_eh : g_xh;
    const float4* r4 = (const float4*)(src + ((size_t)row << 8));
    float4* h4 = (float4*)(hi + ((size_t)row << 8));
    float s = 0.0f;
#pragma unroll
    for (int j = 0; j < 2; ++j) {
        float4 v = r4[lane + 32 * j];
        float4 h;
        h.x = tf32r(v.x); h.y = tf32r(v.y); h.z = tf32r(v.z); h.w = tf32r(v.w);
        h4[lane + 32 * j] = h;
        s += v.x * v.x + v.y * v.y + v.z * v.z + v.w * v.w;
    }
#pragma unroll
    for (int o = 16; o > 0; o >>= 1) s += __shfl_xor_sync(0xffffffffu, s, o);
    if (lane == 0) {
        if (which) g_normE[row] = s; else g_normX[row] = s;
    }
}

// ---------------- 16-warp single-pass TF32 distance GEMM + smem best-2 sketch ----------------
// warp grid 2(M) x 8(N); warp tile 64x32; per-thread acc 4x4x4
__global__ __launch_bounds__(512, 1)
void mma_argmin_kernel() {
    extern __shared__ char smem[];
    uint32_t sb = s2u(smem);
    float* sne = (float*)(smem + OFF_SNE);
    float* sV1 = (float*)(smem + OFF_RED);          // [32][128]
    float* sV2 = sV1 + 4096;
    int*   sI1 = (int*)(sV2 + 4096);
    int*   sI2 = sI1 + 4096;

    int tid = threadIdx.x, wid = tid >> 5, lane = tid & 31;
    int warp_m = wid & 1, warp_n = wid >> 1;        // 2 x 8
    int lg = lane >> 2, lt = lane & 3;
    int row0 = blockIdx.x * BM;
    int slot = warp_n * 4 + lt;                     // 32 slots

    for (int i = tid; i < MC; i += 512) sne[i] = g_normE[i];
    for (int i = tid; i < 4096; i += 512) {
        sV1[i] = FINF; sV2[i] = FINF; sI1[i] = IMAX; sI2[i] = IMAX;
    }

    float nx8[8];
#pragma unroll
    for (int mt = 0; mt < 4; ++mt)
#pragma unroll
        for (int i = 0; i < 2; ++i)
            nx8[mt * 2 + i] = g_normX[row0 + warp_m * 64 + mt * 16 + i * 8 + lg];

    float acc[4][4][4];
#pragma unroll
    for (int mt = 0; mt < 4; ++mt)
#pragma unroll
        for (int n8 = 0; n8 < 4; ++n8)
#pragma unroll
            for (int q = 0; q < 4; ++q) acc[mt][n8][q] = 0.0f;

    // loaders: A = 1024 16B-segs (2/thread), B = 2048 (4/thread)
    int a_r = tid >> 2, a_s = (tid & 3) * 2;        // A row, first seg
    int b_r = tid >> 1, b_s = (tid & 1) * 4;        // B row, first seg
    auto load_chunk = [&](int c) {
        int nt = c >> 3, kc = c & 7;
        int kbase = kc * KC;
        uint32_t stage = sb + OFF_STAGE + (c & 1) * STAGE_BYTES;
        const float* asrc = g_xh + ((size_t)(row0 + a_r) << 8) + kbase + a_s * 4;
        uint32_t adst = stage + a_r * (LDP * 4) + a_s * 16;
        CP_ASYNC16(adst,      asrc);
        CP_ASYNC16(adst + 16, asrc + 4);
        const float* bsrc = g_eh + ((size_t)(nt * BN + b_r) << 8) + kbase + b_s * 4;
        uint32_t bdst = stage + A_BYTES + b_r * (LDP * 4) + b_s * 16;
#pragma unroll
        for (int j = 0; j < 4; ++j) CP_ASYNC16(bdst + j * 16, bsrc + j * 4);
    };

    __syncthreads();   // sne/red ready
    load_chunk(0); CP_COMMIT();

    for (int c = 0; c < NCHUNKS; ++c) {
        if (c + 1 < NCHUNKS) { load_chunk(c + 1); CP_COMMIT(); CP_WAIT(1); }
        else CP_WAIT(0);
        __syncthreads();

        const float* As = (const float*)(smem + OFF_STAGE + (c & 1) * STAGE_BYTES);
        const float* Bs = As + BM * LDP;

#pragma unroll
        for (int ks = 0; ks < 4; ++ks) {
            int k0 = ks * 8;
            uint32_t a[4][4], b[4][2];
#pragma unroll
            for (int mt = 0; mt < 4; ++mt) {
                int r = warp_m * 64 + mt * 16 + lg;
                a[mt][0] = *(const uint32_t*)&As[r * LDP + k0 + lt];
                a[mt][1] = *(const uint32_t*)&As[(r + 8) * LDP + k0 + lt];
                a[mt][2] = *(const uint32_t*)&As[r * LDP + k0 + 4 + lt];
                a[mt][3] = *(const uint32_t*)&As[(r + 8) * LDP + k0 + 4 + lt];
            }
#pragma unroll
            for (int n8 = 0; n8 < 4; ++n8) {
                int cn = warp_n * 32 + n8 * 8 + lg;
                b[n8][0] = *(const uint32_t*)&Bs[cn * LDP + k0 + lt];
                b[n8][1] = *(const uint32_t*)&Bs[cn * LDP + k0 + 4 + lt];
            }
#pragma unroll
            for (int mt = 0; mt < 4; ++mt)
#pragma unroll
                for (int n8 = 0; n8 < 4; ++n8)
                    mma_tf32(acc[mt][n8][0], acc[mt][n8][1], acc[mt][n8][2], acc[mt][n8][3],
                             a[mt][0], a[mt][1], a[mt][2], a[mt][3], b[n8][0], b[n8][1]);
        }

        if ((c & 7) == 7) {
            int nt = c >> 3;
#pragma unroll
            for (int mt = 0; mt < 4; ++mt)
#pragma unroll
                for (int i = 0; i < 2; ++i) {
                    int rl = warp_m * 64 + mt * 16 + i * 8 + lg;
                    float nx = nx8[mt * 2 + i];
                    float tv1 = FINF, tv2 = FINF; int ti1 = IMAX, ti2 = IMAX;
#pragma unroll
                    for (int n8 = 0; n8 < 4; ++n8) {
                        int cbase = nt * BN + warp_n * 32 + n8 * 8 + 2 * lt;
#pragma unroll
                        for (int q = 0; q < 2; ++q) {
                            float dot = acc[mt][n8][i * 2 + q];
                            float d = (sne[cbase + q] + nx) - 2.0f * dot;
                            int cc = cbase + q;
                            if (d < tv1 || (d == tv1 && cc < ti1)) {
                                tv2 = tv1; ti2 = ti1; tv1 = d; ti1 = cc;
                            } else if (d < tv2 || (d == tv2 && cc < ti2)) {
                                tv2 = d; ti2 = cc;
                            }
                        }
                    }
                    int o = slot * 128 + rl;
                    float mv1 = sV1[o], mv2 = sV2[o]; int mi1 = sI1[o], mi2 = sI2[o];
                    if (tv1 < mv1 || (tv1 == mv1 && ti1 < mi1)) {
                        mv2 = mv1; mi2 = mi1; mv1 = tv1; mi1 = ti1;
                    } else if (tv1 < mv2 || (tv1 == mv2 && ti1 < mi2)) {
                        mv2 = tv1; mi2 = ti1;
                    }
                    if (tv2 < mv1 || (tv2 == mv1 && ti2 < mi1)) {
                        mv2 = mv1; mi2 = mi1; mv1 = tv2; mi1 = ti2;
                    } else if (tv2 < mv2 || (tv2 == mv2 && ti2 < mi2)) {
                        mv2 = tv2; mi2 = ti2;
                    }
                    sV1[o] = mv1; sV2[o] = mv2; sI1[o] = mi1; sI2[o] = mi2;
                }
#pragma unroll
            for (int mt = 0; mt < 4; ++mt)
#pragma unroll
                for (int n8 = 0; n8 < 4; ++n8)
#pragma unroll
                    for (int q = 0; q < 4; ++q) acc[mt][n8][q] = 0.0f;
        }
        __syncthreads();   // all reads of stage (c&1) done before overwrite
    }

    // per-row top-8 of 32 slots x best-2 = 64 candidates
    if (tid < BM) {
        unsigned usedA = 0, usedB = 0;
#pragma unroll 1
        for (int sel = 0; sel < NCAND; ++sel) {
            float bv = FINF; int bi = IMAX; int bs = 0; int barr = 0;
            for (int s = 0; s < 32; ++s) {
                float v1 = sV1[s * 128 + tid]; int i1 = sI1[s * 128 + tid];
                float v2 = sV2[s * 128 + tid]; int i2 = sI2[s * 128 + tid];
                bool okA = !((usedA >> s) & 1u), okB = !((usedB >> s) & 1u);
                if (okA && (v1 < bv || (v1 == bv && i1 < bi))) { bv = v1; bi = i1; bs = s; barr = 0; }
                if (okB && (v2 < bv || (v2 == bv && i2 < bi))) { bv = v2; bi = i2; bs = s; barr = 1; }
            }
            if (barr) usedB |= 1u << bs; else usedA |= 1u << bs;
            g_cand[(size_t)(row0 + tid) * NCAND + sel] = bi;
        }
    }
}

// ---------------- fused refine (SERIAL-chain exact fp32) + gather + loss + histogram ----------------
// 4 warps/block, warp per row. Stage x + 8 candidate rows in smem (coalesced),
// lanes 0-7 each run the bitwise-R4 serial FMA chain for one candidate.
__global__ __launch_bounds__(128, 8)
void refine_gather_kernel(const float* __restrict__ x, const float* __restrict__ emb,
                          float* __restrict__ d_out, long long idx_off, int write_idx) {
    __shared__ float sx[4][D];            // x rows
    __shared__ float se[4][NCAND * ELD];  // candidate rows, stride ELD
    int warp = threadIdx.x >> 5, lane = threadIdx.x & 31;
    int row = blockIdx.x * 4 + warp;

    int ci = 0;
    if (lane < NCAND) ci = g_cand[(size_t)row * NCAND + lane];
    int cj[NCAND];
#pragma unroll
    for (int j = 0; j < NCAND; ++j) cj[j] = __shfl_sync(0xffffffffu, ci, j);

    // stage x row (coalesced)
    const float4* x4 = (const float4*)(x + ((size_t)row << 8));
    float4 xv0 = x4[lane], xv1 = x4[lane + 32];
    *(float4*)&sx[warp][lane * 4]        = xv0;
    *(float4*)&sx[warp][128 + lane * 4]  = xv1;

    // stage candidate rows (coalesced, stride ELD)
#pragma unroll
    for (int j = 0; j < NCAND; ++j) {
        const float4* e4 = (const float4*)(emb + ((size_t)cj[j] << 8));
        *(float4*)&se[warp][j * ELD + lane * 4]       = __ldg(&e4[lane]);
        *(float4*)&se[warp][j * ELD + 128 + lane * 4] = __ldg(&e4[lane + 32]);
    }
    __syncwarp();

    // lanes 0-7: serial FMA chain over k (identical order to R1/R4/R6 passing refine)
    float myd = FINF;
    if (lane < NCAND) {
        const float* xs = sx[warp];
        const float* es = &se[warp][lane * ELD];
        float dot = 0.0f;
#pragma unroll 8
        for (int k4 = 0; k4 < 64; ++k4) {
            float4 xv = *(const float4*)&xs[k4 * 4];
            float4 ev = *(const float4*)&es[k4 * 4];
            dot = fmarn(xv.x, ev.x, dot);
            dot = fmarn(xv.y, ev.y, dot);
            dot = fmarn(xv.z, ev.z, dot);
            dot = fmarn(xv.w, ev.w, dot);
        }
        myd = (g_normX[row] + g_normE[cj[lane]]) - 2.0f * dot;
    }
    // broadcast the 8 distances; every lane runs the same serial argmin
    float dv[NCAND];
#pragma unroll
    for (int j = 0; j < NCAND; ++j) dv[j] = __shfl_sync(0xffffffffu, myd, j);
    float bv = FINF; int bi = IMAX; int bj = 0;
#pragma unroll
    for (int j = 0; j < NCAND; ++j) {
        if (dv[j] < bv || (dv[j] == bv && cj[j] < bi)) { bv = dv[j]; bi = cj[j]; bj = j; }
    }
    if (lane == 0 && write_idx) d_out[idx_off + row] = (float)bi;

    // gather from smem (winner row already staged) + straight-through + loss + histogram
    const float* qs = &se[warp][bj * ELD];
    float4* o4 = (float4*)(d_out + ((size_t)row << 8));
    float s = 0.0f;
    {
        float4 q = *(const float4*)&qs[lane * 4];
        float4 o;
        o.x = xv0.x + (q.x - xv0.x); o.y = xv0.y + (q.y - xv0.y);
        o.z = xv0.z + (q.z - xv0.z); o.w = xv0.w + (q.w - xv0.w);
        o4[lane] = o;
        float dx = xv0.x - q.x, dy = xv0.y - q.y, dz = xv0.z - q.z, dw = xv0.w - q.w;
        s += dx * dx + dy * dy + dz * dz + dw * dw;
    }
    {
        float4 q = *(const float4*)&qs[128 + lane * 4];
        float4 o;
        o.x = xv1.x + (q.x - xv1.x); o.y = xv1.y + (q.y - xv1.y);
        o.z = xv1.z + (q.z - xv1.z); o.w = xv1.w + (q.w - xv1.w);
        o4[lane + 32] = o;
        float dx = xv1.x - q.x, dy = xv1.y - q.y, dz = xv1.z - q.z, dw = xv1.w - q.w;
        s += dx * dx + dy * dy + dz * dz + dw * dw;
    }
#pragma unroll
    for (int o = 16; o > 0; o >>= 1) s += __shfl_xor_sync(0xffffffffu, s, o);
    if (lane == 0) {
        atomicAdd(&g_sumsq, s);
        atomicAdd(&g_counts[bi], 1.0f);
    }
}

// ---------------- loss + perplexity ----------------
__global__ void finalize_kernel(float* __restrict__ d_out, long long loss_off,
                                long long perp_off) {
    __shared__ float red[1024];
    int t = threadIdx.x;
    float p = g_counts[t] * (1.0f / (float)NTOK);
    red[t] = p * logf(p + 1e-10f);
    __syncthreads();
    for (int s = 512; s > 0; s >>= 1) {
        if (t < s) red[t] += red[t + s];
        __syncthreads();
    }
    if (t == 0) {
        d_out[loss_off] = 0.25f * g_sumsq / ((float)NTOK * (float)D);
        d_out[perp_off] = expf(-red[0]);
    }
}

// ---------------- launch ----------------
extern "C" void kernel_launch(void* const* d_in, const int* in_sizes, int n_in,
                              void* d_out, int out_size) {
    const float* x   = (const float*)d_in[0];
    const float* emb = (const float*)d_in[1];
    float* out = (float*)d_out;

    int NT = in_sizes[0] / D;
    long long qn = (long long)in_sizes[0];
    long long loss_off = qn;
    long long idx_off  = qn + 1;
    long long perp_off = qn + 1 + NT;
    int full = (out_size >= (int)(qn + NT + 2)) ? 1 : 0;

    cudaFuncSetAttribute(mma_argmin_kernel, cudaFuncAttributeMaxDynamicSharedMemorySize,
                         SMEM_TOTAL);

    init_kernel<<<1, 1024>>>();
    split_kernel<<<NT / 8, 256>>>(x, 0);
    split_kernel<<<MC / 8, 256>>>(emb, 1);
    mma_argmin_kernel<<<NT / BM, 512, SMEM_TOTAL>>>();
    refine_gather_kernel<<<NT / 4, 128>>>(x, emb, out, idx_off, full);
    if (full) finalize_kernel<<<1, 1024>>>(out, loss_off, perp_off);
}